// round 1
// baseline (speedup 1.0000x reference)
#include <cuda_runtime.h>

#define Bn  2
#define Tn  4096
#define Dn  512
#define Hn  8
#define DKn 64
#define Mn  (Bn*Tn)   // 8192

// Scratch (allocation-free rule: __device__ globals)
__device__ float g_Q[Bn*Hn*Tn*DKn];
__device__ float g_K[Bn*Hn*Tn*DKn];
__device__ float g_V[Bn*Hn*Tn*DKn];
__device__ float g_O[Bn*Tn*Dn];

// ---------------------------------------------------------------------------
// GEMM: C[m,n] = sum_k A[m,k] * W[n,k]   (A row-major [M,512], W row-major [512,512])
// MODE 0: plain store to C [M,512]
// MODE 1: QKV — blockIdx.z selects W in {W0,W1,W2}, scatter to g_Q/g_K/g_V in
//         [B,H,T,dk] layout.
// Tile 128x128, k-chunk 64, 8x8 microtile with strided mapping
// (r = ty + 16*i, c = tx + 16*j), smem row stride 68 floats for conflict-light
// float4 reads along k.
// ---------------------------------------------------------------------------
template<int MODE>
__global__ __launch_bounds__(256)
void gemm_nt_kernel(const float* __restrict__ A,
                    const float* __restrict__ W0,
                    const float* __restrict__ W1,
                    const float* __restrict__ W2,
                    float* __restrict__ C)
{
    extern __shared__ float sm[];
    float* As = sm;               // [128][68]
    float* Bs = sm + 128*68;      // [128][68]

    const float* W = W0;
    if (MODE == 1) {
        if (blockIdx.z == 1)      W = W1;
        else if (blockIdx.z == 2) W = W2;
    }

    const int m0 = blockIdx.x * 128;
    const int n0 = blockIdx.y * 128;
    const int tid = threadIdx.x;
    const int tx = tid & 15;
    const int ty = tid >> 4;

    float acc[8][8];
    #pragma unroll
    for (int i = 0; i < 8; i++)
        #pragma unroll
        for (int j = 0; j < 8; j++) acc[i][j] = 0.f;

    for (int k0 = 0; k0 < Dn; k0 += 64) {
        #pragma unroll
        for (int l = 0; l < 8; l++) {
            int idx = tid + l * 256;          // 0..2047 float4 slots
            int r   = idx >> 4;               // 0..127
            int c4  = (idx & 15) << 2;        // 0..60 step 4
            *(float4*)&As[r*68 + c4] = *(const float4*)&A[(size_t)(m0 + r)*Dn + k0 + c4];
            *(float4*)&Bs[r*68 + c4] = *(const float4*)&W[(size_t)(n0 + r)*Dn + k0 + c4];
        }
        __syncthreads();

        #pragma unroll
        for (int k = 0; k < 64; k += 4) {
            float4 a[8];
            #pragma unroll
            for (int i = 0; i < 8; i++)
                a[i] = *(float4*)&As[(ty + 16*i)*68 + k];
            #pragma unroll
            for (int j = 0; j < 8; j++) {
                float4 b = *(float4*)&Bs[(tx + 16*j)*68 + k];
                #pragma unroll
                for (int i = 0; i < 8; i++) {
                    acc[i][j] += a[i].x * b.x;
                    acc[i][j] += a[i].y * b.y;
                    acc[i][j] += a[i].z * b.z;
                    acc[i][j] += a[i].w * b.w;
                }
            }
        }
        __syncthreads();
    }

    if (MODE == 0) {
        #pragma unroll
        for (int i = 0; i < 8; i++) {
            int m = m0 + ty + 16*i;
            #pragma unroll
            for (int j = 0; j < 8; j++) {
                int n = n0 + tx + 16*j;
                C[(size_t)m*Dn + n] = acc[i][j];
            }
        }
    } else {
        float* out = (blockIdx.z == 0) ? g_Q : (blockIdx.z == 1) ? g_K : g_V;
        #pragma unroll
        for (int i = 0; i < 8; i++) {
            int m = m0 + ty + 16*i;
            int b = m / Tn, t = m % Tn;
            #pragma unroll
            for (int j = 0; j < 8; j++) {
                int n = n0 + tx + 16*j;
                int h = n >> 6, d = n & 63;
                out[(((size_t)(b*Hn + h))*Tn + t)*DKn + d] = acc[i][j];
            }
        }
    }
}

// ---------------------------------------------------------------------------
// Flash attention: one block = 64 query rows of one (b,h). Streams 64-key
// tiles. V kept TRANSPOSED in smem so the PV GEMM also reduces over the
// contiguous dim with float4 LDS. Online softmax, 16-lane shfl reductions.
// smem: Qs,Ks,Vt,Ps each [64][68] -> 69632 B total.
// ---------------------------------------------------------------------------
__global__ __launch_bounds__(256)
void flash_kernel()
{
    extern __shared__ float sm[];
    float* Qs = sm;               // [64][68]  (pre-scaled by 1/sqrt(dk))
    float* Ks = sm + 1*64*68;     // [64][68]  row-major [t][d]
    float* Vt = sm + 2*64*68;     // [64][68]  TRANSPOSED [d][t]
    float* Ps = sm + 3*64*68;     // [64][68]  probabilities

    const int bh = blockIdx.y;            // 0..15
    const int q0 = blockIdx.x * 64;
    const float* Qg = g_Q + (size_t)bh * Tn * DKn;
    const float* Kg = g_K + (size_t)bh * Tn * DKn;
    const float* Vg = g_V + (size_t)bh * Tn * DKn;

    const int tid = threadIdx.x;
    const int tx = tid & 15;
    const int ty = tid >> 4;

    // Load Q tile with scale 1/sqrt(64) = 0.125 folded in.
    #pragma unroll
    for (int l = 0; l < 4; l++) {
        int idx = tid + l * 256;          // 0..1023 float4 slots
        int r   = idx >> 4;
        int c4  = (idx & 15) << 2;
        float4 q = *(const float4*)&Qg[(size_t)(q0 + r)*DKn + c4];
        q.x *= 0.125f; q.y *= 0.125f; q.z *= 0.125f; q.w *= 0.125f;
        *(float4*)&Qs[r*68 + c4] = q;
    }

    float m_i[4], l_i[4], o[4][4];
    #pragma unroll
    for (int i = 0; i < 4; i++) {
        m_i[i] = -1e30f; l_i[i] = 0.f;
        #pragma unroll
        for (int j = 0; j < 4; j++) o[i][j] = 0.f;
    }
    __syncthreads();

    for (int kt = 0; kt < Tn; kt += 64) {
        // Load K (row-major) and V (transposed).
        #pragma unroll
        for (int l = 0; l < 4; l++) {
            int idx = tid + l * 256;
            int r   = idx >> 4;
            int c4  = (idx & 15) << 2;
            *(float4*)&Ks[r*68 + c4] = *(const float4*)&Kg[(size_t)(kt + r)*DKn + c4];
            float4 v = *(const float4*)&Vg[(size_t)(kt + r)*DKn + c4];
            Vt[(c4 + 0)*68 + r] = v.x;
            Vt[(c4 + 1)*68 + r] = v.y;
            Vt[(c4 + 2)*68 + r] = v.z;
            Vt[(c4 + 3)*68 + r] = v.w;
        }
        __syncthreads();

        // S = Q K^T  (4x4 microtile: rows ty+16i, cols tx+16j)
        float s[4][4];
        #pragma unroll
        for (int i = 0; i < 4; i++)
            #pragma unroll
            for (int j = 0; j < 4; j++) s[i][j] = 0.f;

        #pragma unroll
        for (int d = 0; d < 64; d += 4) {
            float4 a[4];
            #pragma unroll
            for (int i = 0; i < 4; i++)
                a[i] = *(float4*)&Qs[(ty + 16*i)*68 + d];
            #pragma unroll
            for (int j = 0; j < 4; j++) {
                float4 b = *(float4*)&Ks[(tx + 16*j)*68 + d];
                #pragma unroll
                for (int i = 0; i < 4; i++) {
                    s[i][j] += a[i].x * b.x;
                    s[i][j] += a[i].y * b.y;
                    s[i][j] += a[i].z * b.z;
                    s[i][j] += a[i].w * b.w;
                }
            }
        }

        // Online softmax update; write P to smem.
        #pragma unroll
        for (int i = 0; i < 4; i++) {
            float mx = fmaxf(fmaxf(s[i][0], s[i][1]), fmaxf(s[i][2], s[i][3]));
            mx = fmaxf(mx, __shfl_xor_sync(0xffffffffu, mx, 1));
            mx = fmaxf(mx, __shfl_xor_sync(0xffffffffu, mx, 2));
            mx = fmaxf(mx, __shfl_xor_sync(0xffffffffu, mx, 4));
            mx = fmaxf(mx, __shfl_xor_sync(0xffffffffu, mx, 8));
            float mnew  = fmaxf(m_i[i], mx);
            float alpha = __expf(m_i[i] - mnew);
            m_i[i] = mnew;
            float rs = 0.f;
            #pragma unroll
            for (int j = 0; j < 4; j++) {
                s[i][j] = __expf(s[i][j] - mnew);
                rs += s[i][j];
            }
            rs += __shfl_xor_sync(0xffffffffu, rs, 1);
            rs += __shfl_xor_sync(0xffffffffu, rs, 2);
            rs += __shfl_xor_sync(0xffffffffu, rs, 4);
            rs += __shfl_xor_sync(0xffffffffu, rs, 8);
            l_i[i] = l_i[i] * alpha + rs;
            #pragma unroll
            for (int j = 0; j < 4; j++) {
                o[i][j] *= alpha;
                Ps[(ty + 16*i)*68 + tx + 16*j] = s[i][j];
            }
        }
        __syncthreads();

        // O += P @ V   (Vt is [d][t]; reduce over t, contiguous in both)
        #pragma unroll
        for (int t4 = 0; t4 < 64; t4 += 4) {
            float4 p[4];
            #pragma unroll
            for (int i = 0; i < 4; i++)
                p[i] = *(float4*)&Ps[(ty + 16*i)*68 + t4];
            #pragma unroll
            for (int j = 0; j < 4; j++) {
                float4 v = *(float4*)&Vt[(tx + 16*j)*68 + t4];
                #pragma unroll
                for (int i = 0; i < 4; i++) {
                    o[i][j] += p[i].x * v.x;
                    o[i][j] += p[i].y * v.y;
                    o[i][j] += p[i].z * v.z;
                    o[i][j] += p[i].w * v.w;
                }
            }
        }
        __syncthreads();
    }

    // Normalize and write O in [B,T,D] layout (D = h*64 + d) so the out-proj
    // is a plain GEMM.
    const int b = bh / Hn;
    const int h = bh % Hn;
    #pragma unroll
    for (int i = 0; i < 4; i++) {
        float inv = 1.0f / l_i[i];
        int t = q0 + ty + 16*i;
        #pragma unroll
        for (int j = 0; j < 4; j++) {
            int d = tx + 16*j;
            g_O[((size_t)(b*Tn + t))*Dn + h*DKn + d] = o[i][j] * inv;
        }
    }
}

// ---------------------------------------------------------------------------
extern "C" void kernel_launch(void* const* d_in, const int* in_sizes, int n_in,
                              void* d_out, int out_size)
{
    const float* x  = (const float*)d_in[0];
    const float* Wq = (const float*)d_in[1];
    const float* Wk = (const float*)d_in[2];
    const float* Wv = (const float*)d_in[3];
    const float* Wo = (const float*)d_in[4];
    float* out = (float*)d_out;

    float* gO = nullptr;
    cudaGetSymbolAddress((void**)&gO, g_O);

    const int smem_gemm  = 2 * 128 * 68 * (int)sizeof(float);  // 69632 B
    const int smem_flash = 4 * 64  * 68 * (int)sizeof(float);  // 69632 B
    cudaFuncSetAttribute(gemm_nt_kernel<1>, cudaFuncAttributeMaxDynamicSharedMemorySize, smem_gemm);
    cudaFuncSetAttribute(gemm_nt_kernel<0>, cudaFuncAttributeMaxDynamicSharedMemorySize, smem_gemm);
    cudaFuncSetAttribute(flash_kernel,      cudaFuncAttributeMaxDynamicSharedMemorySize, smem_flash);

    // 1) Fused QKV projections: grid.z selects Wq/Wk/Wv, scatter to per-head layout.
    dim3 gq(Mn/128, Dn/128, 3);
    gemm_nt_kernel<1><<<gq, 256, smem_gemm>>>(x, Wq, Wk, Wv, nullptr);

    // 2) Flash attention over 64-row q-tiles per (b,h).
    dim3 gf(Tn/64, Bn*Hn, 1);
    flash_kernel<<<gf, 256, smem_flash>>>();

    // 3) Output projection -> d_out.
    dim3 go(Mn/128, Dn/128, 1);
    gemm_nt_kernel<0><<<go, 256, smem_gemm>>>(gO, Wo, Wo, Wo, out);
}

// round 5
// speedup vs baseline: 3.2274x; 3.2274x over previous
#include <cuda_runtime.h>
#include <cstdint>

#define Bn  2
#define Tn  4096
#define Dn  512
#define Hn  8
#define DKn 64
#define Mn  (Bn*Tn)   // 8192

// Scratch (allocation-free rule: __device__ globals)
__device__ float g_Q[Bn*Hn*Tn*DKn];
__device__ float g_K[Bn*Hn*Tn*DKn];
__device__ float g_V[Bn*Hn*Tn*DKn];
__device__ float g_O[Bn*Tn*Dn];

__device__ __forceinline__ uint32_t f2tf(float f) {
    uint32_t u; asm("cvt.rna.tf32.f32 %0, %1;" : "=r"(u) : "f"(f)); return u;
}

__device__ __forceinline__ void mma8(float* c,
                                     uint32_t a0, uint32_t a1, uint32_t a2, uint32_t a3,
                                     uint32_t b0, uint32_t b1) {
    asm volatile(
        "mma.sync.aligned.m16n8k8.row.col.f32.tf32.tf32.f32 "
        "{%0,%1,%2,%3},{%4,%5,%6,%7},{%8,%9},{%0,%1,%2,%3};\n"
        : "+f"(c[0]), "+f"(c[1]), "+f"(c[2]), "+f"(c[3])
        : "r"(a0), "r"(a1), "r"(a2), "r"(a3), "r"(b0), "r"(b1));
}

// ---------------------------------------------------------------------------
// TF32 GEMM: C[m,n] = sum_k A[m,k] * W[n,k]
// MODE 0: store to C [M,512].  MODE 1: blockIdx.z selects Wq/Wk/Wv, scatter
// to g_Q/g_K/g_V in [B,H,T,dk] layout.
// CTA tile 128x128, 8 warps (2x4), warp tile 64x32, k-chunk 32.
// ---------------------------------------------------------------------------
template<int MODE>
__global__ __launch_bounds__(256)
void gemm_tf32(const float* __restrict__ A,
               const float* __restrict__ W0,
               const float* __restrict__ W1,
               const float* __restrict__ W2,
               float* __restrict__ C)
{
    __shared__ uint32_t As[128][36];
    __shared__ uint32_t Bs[128][36];

    const float* W = W0;
    if (MODE == 1) {
        if (blockIdx.z == 1)      W = W1;
        else if (blockIdx.z == 2) W = W2;
    }

    const int m0 = blockIdx.x * 128;
    const int n0 = blockIdx.y * 128;
    const int tid  = threadIdx.x;
    const int lane = tid & 31;
    const int wid  = tid >> 5;
    const int gid  = lane >> 2;      // 0..7
    const int tig  = lane & 3;       // 0..3
    const int wm = (wid & 1) * 64;   // warp m offset
    const int wn = (wid >> 1) * 32;  // warp n offset

    float acc[4][4][4];
    #pragma unroll
    for (int i = 0; i < 4; i++)
        #pragma unroll
        for (int j = 0; j < 4; j++)
            #pragma unroll
            for (int q = 0; q < 4; q++) acc[i][j][q] = 0.f;

    for (int k0 = 0; k0 < Dn; k0 += 32) {
        #pragma unroll
        for (int l = 0; l < 4; l++) {
            int idx = tid + l * 256;        // 0..1023
            int r   = idx >> 3;             // 0..127
            int c4  = (idx & 7) << 2;       // 0..28
            float4 a = *(const float4*)&A[(size_t)(m0 + r)*Dn + k0 + c4];
            float4 w = *(const float4*)&W[(size_t)(n0 + r)*Dn + k0 + c4];
            uint4 ua = make_uint4(f2tf(a.x), f2tf(a.y), f2tf(a.z), f2tf(a.w));
            uint4 uw = make_uint4(f2tf(w.x), f2tf(w.y), f2tf(w.z), f2tf(w.w));
            *(uint4*)&As[r][c4] = ua;
            *(uint4*)&Bs[r][c4] = uw;
        }
        __syncthreads();

        #pragma unroll
        for (int kk = 0; kk < 32; kk += 8) {
            uint32_t af[4][4];
            #pragma unroll
            for (int i = 0; i < 4; i++) {
                int rb = wm + i*16 + gid;
                af[i][0] = As[rb    ][kk + tig];
                af[i][1] = As[rb + 8][kk + tig];
                af[i][2] = As[rb    ][kk + tig + 4];
                af[i][3] = As[rb + 8][kk + tig + 4];
            }
            #pragma unroll
            for (int j = 0; j < 4; j++) {
                int nb = wn + j*8 + gid;
                uint32_t b0 = Bs[nb][kk + tig];
                uint32_t b1 = Bs[nb][kk + tig + 4];
                #pragma unroll
                for (int i = 0; i < 4; i++)
                    mma8(acc[i][j], af[i][0], af[i][1], af[i][2], af[i][3], b0, b1);
            }
        }
        __syncthreads();
    }

    // Epilogue: c0,c1 at (row, 2tig), (row, 2tig+1); c2,c3 at row+8.
    #pragma unroll
    for (int i = 0; i < 4; i++) {
        int r0 = m0 + wm + i*16 + gid;
        int r1 = r0 + 8;
        #pragma unroll
        for (int j = 0; j < 4; j++) {
            int n = n0 + wn + j*8 + 2*tig;
            if (MODE == 0) {
                *(float2*)&C[(size_t)r0*Dn + n] = make_float2(acc[i][j][0], acc[i][j][1]);
                *(float2*)&C[(size_t)r1*Dn + n] = make_float2(acc[i][j][2], acc[i][j][3]);
            } else {
                float* out = (blockIdx.z == 0) ? g_Q : (blockIdx.z == 1) ? g_K : g_V;
                int h = n >> 6, d = n & 63;
                int b0r = r0 / Tn, t0 = r0 % Tn;
                int b1r = r1 / Tn, t1 = r1 % Tn;
                *(float2*)&out[(((size_t)(b0r*Hn + h))*Tn + t0)*DKn + d] =
                    make_float2(acc[i][j][0], acc[i][j][1]);
                *(float2*)&out[(((size_t)(b1r*Hn + h))*Tn + t1)*DKn + d] =
                    make_float2(acc[i][j][2], acc[i][j][3]);
            }
        }
    }
}

// ---------------------------------------------------------------------------
// Flash attention with TF32 mma. CTA = 256 q-rows of one (b,h); 8 warps,
// each owning 32 q-rows x full 64-key tile. Online softmax is warp-local.
// P round-trips through smem (tf32) to re-fragment for the PV mma.
// smem layout (uint32): Qs[256][68] | Ks[64][68] | Vs[64][68] | Ps[256][68]
// ---------------------------------------------------------------------------
#define QROWS 256
#define SSTR  68

__global__ __launch_bounds__(256)
void flash_tf32()
{
    extern __shared__ uint32_t sm[];
    uint32_t* Qs = sm;                         // [256][68]
    uint32_t* Ks = Qs + QROWS*SSTR;            // [64][68]
    uint32_t* Vs = Ks + 64*SSTR;               // [64][68]
    uint32_t* Ps = Vs + 64*SSTR;               // [256][68]

    const int bh = blockIdx.y;                 // 0..15
    const int q0 = blockIdx.x * QROWS;
    const float* Qg = g_Q + (size_t)bh * Tn * DKn;
    const float* Kg = g_K + (size_t)bh * Tn * DKn;
    const float* Vg = g_V + (size_t)bh * Tn * DKn;

    const int tid  = threadIdx.x;
    const int lane = tid & 31;
    const int wid  = tid >> 5;
    const int gid  = lane >> 2;
    const int tig  = lane & 3;
    const int rb   = wid * 32;                 // warp's q-row base (in tile)

    // Load Q tile, fold in 1/sqrt(dk)=0.125, convert to tf32.
    #pragma unroll
    for (int l = 0; l < 16; l++) {
        int idx = tid + l * 256;               // 0..4095 float4 slots
        int r   = idx >> 4;
        int c4  = (idx & 15) << 2;
        float4 q = *(const float4*)&Qg[(size_t)(q0 + r)*DKn + c4];
        *(uint4*)&Qs[r*SSTR + c4] = make_uint4(
            f2tf(q.x*0.125f), f2tf(q.y*0.125f), f2tf(q.z*0.125f), f2tf(q.w*0.125f));
    }

    float o[2][8][4];
    float m_i[2][2], l_i[2][2];
    #pragma unroll
    for (int mi = 0; mi < 2; mi++) {
        m_i[mi][0] = m_i[mi][1] = -1e30f;
        l_i[mi][0] = l_i[mi][1] = 0.f;
        #pragma unroll
        for (int j = 0; j < 8; j++)
            #pragma unroll
            for (int q = 0; q < 4; q++) o[mi][j][q] = 0.f;
    }
    __syncthreads();

    for (int kt = 0; kt < Tn; kt += 64) {
        // Load K and V tiles (row-major, tf32).
        #pragma unroll
        for (int l = 0; l < 4; l++) {
            int idx = tid + l * 256;           // 0..1023
            int r   = idx >> 4;
            int c4  = (idx & 15) << 2;
            float4 k = *(const float4*)&Kg[(size_t)(kt + r)*DKn + c4];
            float4 v = *(const float4*)&Vg[(size_t)(kt + r)*DKn + c4];
            *(uint4*)&Ks[r*SSTR + c4] = make_uint4(f2tf(k.x), f2tf(k.y), f2tf(k.z), f2tf(k.w));
            *(uint4*)&Vs[r*SSTR + c4] = make_uint4(f2tf(v.x), f2tf(v.y), f2tf(v.z), f2tf(v.w));
        }
        __syncthreads();

        // S = Q K^T : per warp 32x64, 2 m-tiles x 8 n-tiles.
        float s[2][8][4];
        #pragma unroll
        for (int mi = 0; mi < 2; mi++)
            #pragma unroll
            for (int j = 0; j < 8; j++)
                #pragma unroll
                for (int q = 0; q < 4; q++) s[mi][j][q] = 0.f;

        #pragma unroll
        for (int kk = 0; kk < 64; kk += 8) {
            uint32_t af[2][4];
            #pragma unroll
            for (int mi = 0; mi < 2; mi++) {
                int r = rb + mi*16 + gid;
                af[mi][0] = Qs[(r    )*SSTR + kk + tig];
                af[mi][1] = Qs[(r + 8)*SSTR + kk + tig];
                af[mi][2] = Qs[(r    )*SSTR + kk + tig + 4];
                af[mi][3] = Qs[(r + 8)*SSTR + kk + tig + 4];
            }
            #pragma unroll
            for (int j = 0; j < 8; j++) {
                uint32_t b0 = Ks[(j*8 + gid)*SSTR + kk + tig];
                uint32_t b1 = Ks[(j*8 + gid)*SSTR + kk + tig + 4];
                #pragma unroll
                for (int mi = 0; mi < 2; mi++)
                    mma8(s[mi][j], af[mi][0], af[mi][1], af[mi][2], af[mi][3], b0, b1);
            }
        }

        // Online softmax (warp-local rows): row0 = c0,c1 ; row1 = c2,c3.
        #pragma unroll
        for (int mi = 0; mi < 2; mi++) {
            float mx0 = -1e30f, mx1 = -1e30f;
            #pragma unroll
            for (int j = 0; j < 8; j++) {
                mx0 = fmaxf(mx0, fmaxf(s[mi][j][0], s[mi][j][1]));
                mx1 = fmaxf(mx1, fmaxf(s[mi][j][2], s[mi][j][3]));
            }
            mx0 = fmaxf(mx0, __shfl_xor_sync(0xffffffffu, mx0, 1));
            mx0 = fmaxf(mx0, __shfl_xor_sync(0xffffffffu, mx0, 2));
            mx1 = fmaxf(mx1, __shfl_xor_sync(0xffffffffu, mx1, 1));
            mx1 = fmaxf(mx1, __shfl_xor_sync(0xffffffffu, mx1, 2));

            float mn0 = fmaxf(m_i[mi][0], mx0);
            float mn1 = fmaxf(m_i[mi][1], mx1);
            float al0 = __expf(m_i[mi][0] - mn0);
            float al1 = __expf(m_i[mi][1] - mn1);
            m_i[mi][0] = mn0; m_i[mi][1] = mn1;

            float rs0 = 0.f, rs1 = 0.f;
            int r = rb + mi*16 + gid;
            #pragma unroll
            for (int j = 0; j < 8; j++) {
                float e0 = __expf(s[mi][j][0] - mn0);
                float e1 = __expf(s[mi][j][1] - mn0);
                float e2 = __expf(s[mi][j][2] - mn1);
                float e3 = __expf(s[mi][j][3] - mn1);
                rs0 += e0 + e1; rs1 += e2 + e3;
                *(uint2*)&Ps[(r    )*SSTR + j*8 + 2*tig] = make_uint2(f2tf(e0), f2tf(e1));
                *(uint2*)&Ps[(r + 8)*SSTR + j*8 + 2*tig] = make_uint2(f2tf(e2), f2tf(e3));
            }
            rs0 += __shfl_xor_sync(0xffffffffu, rs0, 1);
            rs0 += __shfl_xor_sync(0xffffffffu, rs0, 2);
            rs1 += __shfl_xor_sync(0xffffffffu, rs1, 1);
            rs1 += __shfl_xor_sync(0xffffffffu, rs1, 2);
            l_i[mi][0] = l_i[mi][0]*al0 + rs0;
            l_i[mi][1] = l_i[mi][1]*al1 + rs1;

            #pragma unroll
            for (int j = 0; j < 8; j++) {
                o[mi][j][0] *= al0; o[mi][j][1] *= al0;
                o[mi][j][2] *= al1; o[mi][j][3] *= al1;
            }
        }
        __syncwarp();

        // O += P @ V : A from Ps (k = key), B from Vs (row-major [key][dk]).
        #pragma unroll
        for (int kk = 0; kk < 64; kk += 8) {
            uint32_t af[2][4];
            #pragma unroll
            for (int mi = 0; mi < 2; mi++) {
                int r = rb + mi*16 + gid;
                af[mi][0] = Ps[(r    )*SSTR + kk + tig];
                af[mi][1] = Ps[(r + 8)*SSTR + kk + tig];
                af[mi][2] = Ps[(r    )*SSTR + kk + tig + 4];
                af[mi][3] = Ps[(r + 8)*SSTR + kk + tig + 4];
            }
            #pragma unroll
            for (int j = 0; j < 8; j++) {
                uint32_t b0 = Vs[(kk + tig    )*SSTR + j*8 + gid];
                uint32_t b1 = Vs[(kk + tig + 4)*SSTR + j*8 + gid];
                #pragma unroll
                for (int mi = 0; mi < 2; mi++)
                    mma8(o[mi][j], af[mi][0], af[mi][1], af[mi][2], af[mi][3], b0, b1);
            }
        }
        __syncthreads();
    }

    // Normalize and write O in [B,T,D] layout (col = h*64 + d).
    const int b = bh >> 3;
    const int h = bh & 7;
    #pragma unroll
    for (int mi = 0; mi < 2; mi++) {
        float inv0 = 1.0f / l_i[mi][0];
        float inv1 = 1.0f / l_i[mi][1];
        int t0 = q0 + rb + mi*16 + gid;
        int t1 = t0 + 8;
        #pragma unroll
        for (int j = 0; j < 8; j++) {
            int d = h*DKn + j*8 + 2*tig;
            *(float2*)&g_O[((size_t)(b*Tn + t0))*Dn + d] =
                make_float2(o[mi][j][0]*inv0, o[mi][j][1]*inv0);
            *(float2*)&g_O[((size_t)(b*Tn + t1))*Dn + d] =
                make_float2(o[mi][j][2]*inv1, o[mi][j][3]*inv1);
        }
    }
}

// ---------------------------------------------------------------------------
extern "C" void kernel_launch(void* const* d_in, const int* in_sizes, int n_in,
                              void* d_out, int out_size)
{
    const float* x  = (const float*)d_in[0];
    const float* Wq = (const float*)d_in[1];
    const float* Wk = (const float*)d_in[2];
    const float* Wv = (const float*)d_in[3];
    const float* Wo = (const float*)d_in[4];
    float* out = (float*)d_out;

    float* gO = nullptr;
    cudaGetSymbolAddress((void**)&gO, g_O);

    const int smem_flash = (QROWS*SSTR + 64*SSTR + 64*SSTR + QROWS*SSTR) * (int)sizeof(uint32_t);
    cudaFuncSetAttribute(flash_tf32, cudaFuncAttributeMaxDynamicSharedMemorySize, smem_flash);

    // 1) QKV projections (tf32 tensor cores), scatter to per-head layout.
    dim3 gq(Mn/128, Dn/128, 3);
    gemm_tf32<1><<<gq, 256>>>(x, Wq, Wk, Wv, nullptr);

    // 2) Flash attention, 256-row q-tiles per (b,h).
    dim3 gf(Tn/QROWS, Bn*Hn, 1);
    flash_tf32<<<gf, 256, smem_flash>>>();

    // 3) Output projection -> d_out.
    dim3 go(Mn/128, Dn/128, 1);
    gemm_tf32<0><<<go, 256>>>(gO, Wo, Wo, Wo, out);
}